// round 16
// baseline (speedup 1.0000x reference)
#include <cuda_runtime.h>
#include <cuda_bf16.h>
#include <math.h>

#define N_ENT    100000
#define N_REL    16
#define DIM      128
#define N_BASES  4
#define N_EDGES  640000
#define BATCH    1024
#define N_NEG    64
#define BN_EPS   1e-5f
#define NSCANB   391          // ceil(N_ENT/256)
#define QENT     25000        // entities per phase (L2-resident agg)

// GEMM geometry: CTA = 256 thr (8 warps), tile M=64, N=128, K-chunk=64
#define A_STRIDE 72                       // bf16 per A row (144 B)
#define ABUF_ELEM (2 * 64 * A_STRIDE)     // bf16 per A buffer (hi+lo planes)
#define W_STRIDE 36                       // u32 per W row (144 B)
#define WBUF_U32 (2 * 128 * W_STRIDE)
#define SMEM_A  (2 * ABUF_ELEM * 2)       // 36864 B (double buffered)
#define SMEM_W  (2 * WBUF_U32 * 4)        // 73728 B (double buffered)
#define SMEM_G  (SMEM_A + SMEM_W)         // 110592 B -> 2 CTAs/SM

// ---------------- device scratch (static) ---------------------------------
__device__ float g_out0[N_ENT * DIM];
__device__ float g_out1[N_ENT * DIM];
__device__ __nv_bfloat16 g_aggh[QENT * 512];   // quarter agg, bf16 hi
__device__ __nv_bfloat16 g_aggl[QENT * 512];   // quarter agg, bf16 lo
__device__ float g_sum[DIM];
__device__ float g_sumsq[DIM];
__device__ float g_scale[DIM];
__device__ float g_shift[DIM];
__device__ float g_invd[N_ENT];           // 1/max(deg,1), built in scan
// counting sort of edges by DST; g_hist doubles as deg
__device__ int g_hist[N_ENT];
__device__ int g_histL[N_ENT];
__device__ int g_bsum[NSCANB];
__device__ int g_cursor[N_ENT];
__device__ int g_total;
__device__ int2 g_est[N_EDGES];           // sorted-by-dst packed (src, type)
// Wfull = [w_sl ; B0..B3] (640 x 128), bf16 hi/lo u32 k-pairs,
// layout [l][n][k2]: idx = (l*128 + n)*320 + k2
__device__ unsigned g_W32h[2 * 128 * 320];
__device__ unsigned g_W32l[2 * 128 * 320];

// ---------------- setup ---------------------------------------------------
__global__ void k_zero_all() {
    int i = blockIdx.x * blockDim.x + threadIdx.x;
    if (i < N_ENT) { g_hist[i] = 0; g_cursor[i] = 0; }
    if (i < DIM) { g_sum[i] = 0.0f; g_sumsq[i] = 0.0f; }
    if (i == 0) g_total = 0;
}

__global__ void k_hist(const int* __restrict__ ei) {
    int e = blockIdx.x * blockDim.x + threadIdx.x;
    if (e < N_EDGES) atomicAdd(&g_hist[ei[N_EDGES + e]], 1);
}

// per-block scan + atomic global offset (cross-block order irrelevant);
// also emits g_invd for free.
__global__ __launch_bounds__(256) void k_scan_part() {
    __shared__ int sm[256];
    int t = threadIdx.x;
    int idx = blockIdx.x * 256 + t;
    int v = (idx < N_ENT) ? g_hist[idx] : 0;
    int x = v;
    sm[t] = x; __syncthreads();
#pragma unroll
    for (int off = 1; off < 256; off <<= 1) {
        int y = (t >= off) ? sm[t - off] : 0;
        __syncthreads();
        x += y; sm[t] = x;
        __syncthreads();
    }
    if (idx < N_ENT) {
        g_histL[idx] = x - v;
        g_invd[idx] = 1.0f / fmaxf((float)v, 1.0f);
    }
    if (t == 255) g_bsum[blockIdx.x] = atomicAdd(&g_total, x);
}

__global__ void k_scatter(const int* __restrict__ ei,
                          const int* __restrict__ et) {
    int e = blockIdx.x * blockDim.x + threadIdx.x;
    if (e >= N_EDGES) return;
    int s = ei[e];
    int d = ei[N_EDGES + e];
    int pos = g_histL[d] + g_bsum[d >> 8] + atomicAdd(&g_cursor[d], 1);
    g_est[pos] = make_int2(s, et[e]);
}

// Wfull rows: k<128 -> w_sl[k][n];  k>=128 -> bases[b][kr][n]
__global__ void k_wcat(const float* __restrict__ w_sl,
                       const float* __restrict__ bases) {
    int idx = blockIdx.x * blockDim.x + threadIdx.x;
    int total = 2 * 128 * 320;
    if (idx >= total) return;
    int l   = idx / (128 * 320);
    int rem = idx - l * (128 * 320);
    int n   = rem / 320;
    int k2  = rem - n * 320;
    int k   = 2 * k2;
    float v0, v1;
    if (k < DIM) {
        v0 = w_sl[l * DIM * DIM + k * DIM + n];
        v1 = w_sl[l * DIM * DIM + (k + 1) * DIM + n];
    } else {
        int kk = k - DIM;
        int b = kk >> 7;
        int kr = kk & 127;
        const float* bp = bases + (l * N_BASES + b) * DIM * DIM;
        v0 = bp[kr * DIM + n];
        v1 = bp[(kr + 1) * DIM + n];
    }
    __nv_bfloat16 h0 = __float2bfloat16(v0);
    __nv_bfloat16 h1 = __float2bfloat16(v1);
    __nv_bfloat16 l0 = __float2bfloat16(v0 - __bfloat162float(h0));
    __nv_bfloat16 l1 = __float2bfloat16(v1 - __bfloat162float(h1));
    __nv_bfloat162 ph(h0, h1), pl(l0, l1);
    g_W32h[idx] = *reinterpret_cast<unsigned*>(&ph);
    g_W32l[idx] = *reinterpret_cast<unsigned*>(&pl);
}

// ---------------- helpers -------------------------------------------------
__device__ __forceinline__ float4 bnrelu4(float4 v, float invd,
                                          float4 sc, float4 sh) {
    v.x = fmaxf(fmaf(v.x * invd, sc.x, sh.x), 0.f);
    v.y = fmaxf(fmaf(v.y * invd, sc.y, sh.y), 0.f);
    v.z = fmaxf(fmaf(v.z * invd, sc.z, sh.z), 0.f);
    v.w = fmaxf(fmaf(v.w * invd, sc.w, sh.w), 0.f);
    return v;
}

__device__ __forceinline__ void acc_edge(float4& a0, float4& a1,
                                         float4& a2, float4& a3,
                                         float4 c, float4 xv) {
    a0.x = fmaf(c.x, xv.x, a0.x); a0.y = fmaf(c.x, xv.y, a0.y);
    a0.z = fmaf(c.x, xv.z, a0.z); a0.w = fmaf(c.x, xv.w, a0.w);
    a1.x = fmaf(c.y, xv.x, a1.x); a1.y = fmaf(c.y, xv.y, a1.y);
    a1.z = fmaf(c.y, xv.z, a1.z); a1.w = fmaf(c.y, xv.w, a1.w);
    a2.x = fmaf(c.z, xv.x, a2.x); a2.y = fmaf(c.z, xv.y, a2.y);
    a2.z = fmaf(c.z, xv.z, a2.z); a2.w = fmaf(c.z, xv.w, a2.w);
    a3.x = fmaf(c.w, xv.x, a3.x); a3.y = fmaf(c.w, xv.y, a3.y);
    a3.z = fmaf(c.w, xv.z, a3.z); a3.w = fmaf(c.w, xv.w, a3.w);
}

__device__ __forceinline__ void mma16816(float* c, const unsigned* a,
                                         const unsigned* b) {
    asm volatile(
        "mma.sync.aligned.m16n8k16.row.col.f32.bf16.bf16.f32 "
        "{%0,%1,%2,%3}, {%4,%5,%6,%7}, {%8,%9}, {%0,%1,%2,%3};\n"
        : "+f"(c[0]), "+f"(c[1]), "+f"(c[2]), "+f"(c[3])
        : "r"(a[0]), "r"(a[1]), "r"(a[2]), "r"(a[3]), "r"(b[0]), "r"(b[1]));
}

__device__ __forceinline__ void ldsm4(unsigned* r, const void* p) {
    unsigned addr = (unsigned)__cvta_generic_to_shared(p);
    asm volatile(
        "ldmatrix.sync.aligned.m8n8.x4.shared.b16 {%0,%1,%2,%3}, [%4];"
        : "=r"(r[0]), "=r"(r[1]), "=r"(r[2]), "=r"(r[3]) : "r"(addr));
}

__device__ __forceinline__ void cp16(void* dst_smem, const void* src) {
    unsigned d = (unsigned)__cvta_generic_to_shared(dst_smem);
    asm volatile("cp.async.cg.shared.global [%0], [%1], 16;\n"
                 :: "r"(d), "l"(src));
}

// ---------------- edge aggregation (one quarter; warp per dst; MLP=4) -----
__global__ __launch_bounds__(256) void k_edge_agg(const float* __restrict__ coeff,
                                                  const float* __restrict__ xext,
                                                  int bnflag, int qbase) {
    __shared__ float csm[N_REL * 4];
    int tid = threadIdx.x;
    if (tid < N_REL * 4) csm[tid] = coeff[tid];
    __syncthreads();

    int d    = qbase + blockIdx.x * 8 + (tid >> 5);
    int lane = tid & 31;
    if (d >= N_ENT) return;

    int start = g_histL[d] + g_bsum[d >> 8];
    int end   = start + g_hist[d];
    const float* __restrict__ xsrc = bnflag ? g_out0 : xext;

    float4 sc, sh;
    if (bnflag) {
        sc = *reinterpret_cast<const float4*>(&g_scale[lane * 4]);
        sh = *reinterpret_cast<const float4*>(&g_shift[lane * 4]);
    }

    float4 a0 = make_float4(0.f, 0.f, 0.f, 0.f);
    float4 a1 = a0, a2 = a0, a3 = a0;

    int e = start;
    for (; e + 3 < end; e += 4) {
        int2 p0 = g_est[e],     p1 = g_est[e + 1];
        int2 p2 = g_est[e + 2], p3 = g_est[e + 3];
        float4 x0 = *reinterpret_cast<const float4*>(&xsrc[p0.x * DIM + lane * 4]);
        float4 x1 = *reinterpret_cast<const float4*>(&xsrc[p1.x * DIM + lane * 4]);
        float4 x2 = *reinterpret_cast<const float4*>(&xsrc[p2.x * DIM + lane * 4]);
        float4 x3 = *reinterpret_cast<const float4*>(&xsrc[p3.x * DIM + lane * 4]);
        if (bnflag) {
            float i0 = g_invd[p0.x], i1 = g_invd[p1.x];
            float i2 = g_invd[p2.x], i3 = g_invd[p3.x];
            x0 = bnrelu4(x0, i0, sc, sh);
            x1 = bnrelu4(x1, i1, sc, sh);
            x2 = bnrelu4(x2, i2, sc, sh);
            x3 = bnrelu4(x3, i3, sc, sh);
        }
        acc_edge(a0, a1, a2, a3,
                 *reinterpret_cast<const float4*>(&csm[p0.y * 4]), x0);
        acc_edge(a0, a1, a2, a3,
                 *reinterpret_cast<const float4*>(&csm[p1.y * 4]), x1);
        acc_edge(a0, a1, a2, a3,
                 *reinterpret_cast<const float4*>(&csm[p2.y * 4]), x2);
        acc_edge(a0, a1, a2, a3,
                 *reinterpret_cast<const float4*>(&csm[p3.y * 4]), x3);
    }
    for (; e < end; e++) {
        int2 p0 = g_est[e];
        float4 x0 = *reinterpret_cast<const float4*>(&xsrc[p0.x * DIM + lane * 4]);
        if (bnflag) x0 = bnrelu4(x0, g_invd[p0.x], sc, sh);
        acc_edge(a0, a1, a2, a3,
                 *reinterpret_cast<const float4*>(&csm[p0.y * 4]), x0);
    }

    float4 acc[4] = {a0, a1, a2, a3};
    int dq = d - qbase;
#pragma unroll
    for (int b = 0; b < 4; b++) {
        float4 a = acc[b];
        __nv_bfloat16 hx = __float2bfloat16(a.x);
        __nv_bfloat16 hy = __float2bfloat16(a.y);
        __nv_bfloat16 hz = __float2bfloat16(a.z);
        __nv_bfloat16 hw = __float2bfloat16(a.w);
        __nv_bfloat16 lx = __float2bfloat16(a.x - __bfloat162float(hx));
        __nv_bfloat16 ly = __float2bfloat16(a.y - __bfloat162float(hy));
        __nv_bfloat16 lz = __float2bfloat16(a.z - __bfloat162float(hz));
        __nv_bfloat16 lw = __float2bfloat16(a.w - __bfloat162float(hw));
        __nv_bfloat162 hp0(hx, hy), hp1(hz, hw), lp0(lx, ly), lp1(lz, lw);
        int off = dq * 512 + b * 128 + lane * 4;
        uint2 hv = make_uint2(*reinterpret_cast<unsigned*>(&hp0),
                              *reinterpret_cast<unsigned*>(&hp1));
        uint2 lv = make_uint2(*reinterpret_cast<unsigned*>(&lp0),
                              *reinterpret_cast<unsigned*>(&lp1));
        *reinterpret_cast<uint2*>(&g_aggh[off]) = hv;
        *reinterpret_cast<uint2*>(&g_aggl[off]) = lv;
    }
}

// ---------------- GEMM (one quarter): out = [x | agg] @ Wfull + bias ------
__device__ __forceinline__ void prefetch_w2(unsigned* wbuf, int layer,
                                            int kc, int tid) {
#pragma unroll
    for (int i = 0; i < 8; i++) {
        int lin = tid + i * 256;          // 0..2047
        int h   = lin >> 10;
        int rem = lin & 1023;
        int n   = rem >> 3;
        int q   = rem & 7;
        const unsigned* src = (h ? g_W32l : g_W32h) +
                              (layer * 128 + n) * 320 + kc * 32 + q * 4;
        cp16(&wbuf[(h * 128 + n) * W_STRIDE + q * 4], src);
    }
}

__device__ __forceinline__ void prefetch_a2(__nv_bfloat16* abuf, int m0,
                                            int qbase, int qlim,
                                            int kc, int tid) {
    int aggc = kc * 64 - 128;             // kc >= 2 always
#pragma unroll
    for (int i = 0; i < 4; i++) {
        int lin = tid + i * 256;          // 0..1023
        int h   = lin >> 9;
        int rem = lin & 511;
        int row = rem >> 3;
        int q   = rem & 7;
        int r = m0 + row; if (r >= qlim) r = qlim - 1;
        const __nv_bfloat16* src = (h ? g_aggl : g_aggh) +
                                   (r - qbase) * 512 + aggc + q * 8;
        cp16(&abuf[(h * 64 + row) * A_STRIDE + q * 8], src);
    }
}

__global__ __launch_bounds__(256, 2) void k_gemm2(int layer,
                                                  const float* __restrict__ xext,
                                                  const float* __restrict__ b_sl,
                                                  int bnflag, int qbase) {
    extern __shared__ unsigned char smraw[];
    __nv_bfloat16* ab = reinterpret_cast<__nv_bfloat16*>(smraw);
    unsigned* wb = reinterpret_cast<unsigned*>(smraw + SMEM_A);

    const float* __restrict__ xsrc = bnflag ? g_out0 : xext;
    float* __restrict__ outbuf = bnflag ? g_out1 : g_out0;
    int qlim = qbase + QENT;
    if (qlim > N_ENT) qlim = N_ENT;

    int tid  = threadIdx.x;
    int lane = tid & 31;
    int wid  = tid >> 5;
    int g    = lane >> 2;
    int tig  = lane & 3;
    int m_base = (wid & 1) * 32;
    int n_base = (wid >> 1) * 32;
    int m0 = qbase + blockIdx.x * 64;

    // prefetch W chunks 0,1
    prefetch_w2(wb, layer, 0, tid);
    asm volatile("cp.async.commit_group;\n" ::: "memory");
    prefetch_w2(wb + WBUF_U32, layer, 1, tid);
    asm volatile("cp.async.commit_group;\n" ::: "memory");

    // x part (K 0..127) -> A buffers 0,1; BN+ReLU opt; split hi/lo
#pragma unroll
    for (int i = 0; i < 8; i++) {
        int lin = tid + i * 256;          // 0..2047 float4
        int row = lin >> 5;               // 0..63
        int q   = lin & 31;
        int c0  = q * 4;
        int mr  = m0 + row;
        float4 v = make_float4(0.f, 0.f, 0.f, 0.f);
        if (mr < qlim) {
            v = *reinterpret_cast<const float4*>(&xsrc[mr * DIM + c0]);
            if (bnflag) {
                float invd = g_invd[mr];
                float4 sc = *reinterpret_cast<const float4*>(&g_scale[c0]);
                float4 sh = *reinterpret_cast<const float4*>(&g_shift[c0]);
                v = bnrelu4(v, invd, sc, sh);
            }
        }
        __nv_bfloat16 h0 = __float2bfloat16(v.x);
        __nv_bfloat16 h1 = __float2bfloat16(v.y);
        __nv_bfloat16 h2 = __float2bfloat16(v.z);
        __nv_bfloat16 h3 = __float2bfloat16(v.w);
        __nv_bfloat16 l0 = __float2bfloat16(v.x - __bfloat162float(h0));
        __nv_bfloat16 l1 = __float2bfloat16(v.y - __bfloat162float(h1));
        __nv_bfloat16 l2 = __float2bfloat16(v.z - __bfloat162float(h2));
        __nv_bfloat16 l3 = __float2bfloat16(v.w - __bfloat162float(h3));
        int buf = c0 >> 6;
        int kl  = c0 & 63;
        __nv_bfloat16* dsth = ab + buf * ABUF_ELEM + row * A_STRIDE + kl;
        __nv_bfloat16* dstl = dsth + 64 * A_STRIDE;
        *reinterpret_cast<__nv_bfloat162*>(dsth)     = __nv_bfloat162(h0, h1);
        *reinterpret_cast<__nv_bfloat162*>(dsth + 2) = __nv_bfloat162(h2, h3);
        *reinterpret_cast<__nv_bfloat162*>(dstl)     = __nv_bfloat162(l0, l1);
        *reinterpret_cast<__nv_bfloat162*>(dstl + 2) = __nv_bfloat162(l2, l3);
    }

    int a_row = m_base + (lane & 15);
    int a_colsel = (lane >> 4) << 3;
    int b_row = n_base + (lane & 7) + ((lane & 16) ? 8 : 0);
    int b_ksel = (lane & 8) ? 4 : 0;

    float C[2][4][4];
#pragma unroll
    for (int mt = 0; mt < 2; mt++)
#pragma unroll
        for (int nt = 0; nt < 4; nt++)
#pragma unroll
            for (int j = 0; j < 4; j++) C[mt][nt][j] = 0.0f;

    for (int kc = 0; kc < 10; kc++) {
        if (kc < 9)
            asm volatile("cp.async.wait_group 1;\n" ::: "memory");
        else
            asm volatile("cp.async.wait_group 0;\n" ::: "memory");
        __syncthreads();

        __nv_bfloat16* acur = ab + (kc & 1) * ABUF_ELEM;
        unsigned* wcur = wb + (kc & 1) * WBUF_U32;

#pragma unroll
        for (int s = 0; s < 4; s++) {
            unsigned A[2][2][4];
#pragma unroll
            for (int h = 0; h < 2; h++)
#pragma unroll
                for (int mt = 0; mt < 2; mt++)
                    ldsm4(A[h][mt],
                          &acur[(h * 64 + a_row + mt * 16) * A_STRIDE +
                                s * 16 + a_colsel]);
            unsigned B[2][2][4];
#pragma unroll
            for (int h = 0; h < 2; h++)
#pragma unroll
                for (int nt2 = 0; nt2 < 2; nt2++)
                    ldsm4(B[h][nt2],
                          &wcur[(h * 128 + b_row + nt2 * 16) * W_STRIDE +
                                s * 8 + b_ksel]);
#pragma unroll
            for (int mt = 0; mt < 2; mt++)
#pragma unroll
                for (int nt = 0; nt < 4; nt++) {
                    const unsigned* bh = &B[0][nt >> 1][(nt & 1) * 2];
                    const unsigned* bl = &B[1][nt >> 1][(nt & 1) * 2];
                    mma16816(C[mt][nt], A[0][mt], bh);
                    mma16816(C[mt][nt], A[0][mt], bl);
                    mma16816(C[mt][nt], A[1][mt], bh);
                }
        }
        __syncthreads();
        if (kc + 2 < 10) {
            prefetch_a2(ab + (kc & 1) * ABUF_ELEM, m0, qbase, qlim, kc + 2, tid);
            prefetch_w2(wb + (kc & 1) * WBUF_U32, layer, kc + 2, tid);
            asm volatile("cp.async.commit_group;\n" ::: "memory");
        }
    }

    // stats scratch aliased onto dead A buffer (all reads done, synced)
    float* ssum = reinterpret_cast<float*>(ab);
    float* ssq  = ssum + 128;
    if (tid < 128) { ssum[tid] = 0.0f; ssq[tid] = 0.0f; }
    __syncthreads();

    float invd_[2][2];
#pragma unroll
    for (int mt = 0; mt < 2; mt++)
#pragma unroll
        for (int j = 0; j < 2; j++) {
            int r = m0 + m_base + mt * 16 + g + j * 8;
            invd_[mt][j] = (r < qlim) ? g_invd[r] : 0.0f;
        }

    const float* __restrict__ bias = b_sl + layer * DIM;
#pragma unroll
    for (int nt = 0; nt < 4; nt++) {
        int col = n_base + nt * 8 + tig * 2;
        float b0 = bias[col], b1 = bias[col + 1];
        float cs0 = 0.f, cq0 = 0.f, cs1 = 0.f, cq1 = 0.f;
#pragma unroll
        for (int mt = 0; mt < 2; mt++) {
            int row0 = m0 + m_base + mt * 16 + g;
            float2 v0 = make_float2(C[mt][nt][0] + b0, C[mt][nt][1] + b1);
            float2 v1 = make_float2(C[mt][nt][2] + b0, C[mt][nt][3] + b1);
            if (row0 < qlim)
                *reinterpret_cast<float2*>(&outbuf[row0 * DIM + col]) = v0;
            if (row0 + 8 < qlim)
                *reinterpret_cast<float2*>(&outbuf[(row0 + 8) * DIM + col]) = v1;
            float w;
            w = v0.x * invd_[mt][0]; cs0 += w; cq0 += w * w;
            w = v0.y * invd_[mt][0]; cs1 += w; cq1 += w * w;
            w = v1.x * invd_[mt][1]; cs0 += w; cq0 += w * w;
            w = v1.y * invd_[mt][1]; cs1 += w; cq1 += w * w;
        }
        atomicAdd(&ssum[col], cs0);
        atomicAdd(&ssq[col], cq0);
        atomicAdd(&ssum[col + 1], cs1);
        atomicAdd(&ssq[col + 1], cq1);
    }
    __syncthreads();
    if (tid < 128) {
        atomicAdd(&g_sum[tid], ssum[tid]);
        atomicAdd(&g_sumsq[tid], ssq[tid]);
    }
}

// ---------------- BN finalize (also resets accumulators) ------------------
__global__ void k_bn_final(int layer, const float* __restrict__ gamma,
                           const float* __restrict__ beta) {
    int c = threadIdx.x;
    if (c >= DIM) return;
    const float INV_N = 1.0f / (float)N_ENT;
    float mu  = g_sum[c] * INV_N;
    float var = g_sumsq[c] * INV_N - mu * mu;
    float rs  = rsqrtf(var + BN_EPS);
    float sc  = rs * gamma[layer * DIM + c];
    g_scale[c] = sc;
    g_shift[c] = beta[layer * DIM + c] - mu * sc;
    g_sum[c] = 0.0f;
    g_sumsq[c] = 0.0f;
}

// ---------------- scoring -------------------------------------------------
__global__ __launch_bounds__(256) void k_score(const int* __restrict__ head,
                                               const int* __restrict__ relidx,
                                               const int* __restrict__ tail,
                                               const int* __restrict__ neg,
                                               const float* __restrict__ rel_tab,
                                               float* __restrict__ out) {
    __shared__ float hr[DIM];
    int b = blockIdx.x;
    int tid = threadIdx.x;
    int h = head[b], r = relidx[b], t = tail[b];
    if (tid < DIM) {
        float invd = g_invd[h];
        float v = g_out1[h * DIM + tid];
        v = fmaxf(fmaf(v * invd, g_scale[tid], g_shift[tid]), 0.f);
        hr[tid] = v + rel_tab[r * DIM + tid];
    }
    __syncthreads();

    int wid = tid >> 5, lane = tid & 31;
    float4 hv = reinterpret_cast<const float4*>(hr)[lane];
    float4 sc = *reinterpret_cast<const float4*>(&g_scale[lane * 4]);
    float4 sh = *reinterpret_cast<const float4*>(&g_shift[lane * 4]);

    for (int j = wid; j < 1 + N_NEG; j += 8) {
        int target = (j == 0) ? t : neg[b * N_NEG + (j - 1)];
        float invd = g_invd[target];
        float4 ev = reinterpret_cast<const float4*>(&g_out1[target * DIM])[lane];
        ev = bnrelu4(ev, invd, sc, sh);
        float dx = hv.x - ev.x, dy = hv.y - ev.y,
              dz = hv.z - ev.z, dw = hv.w - ev.w;
        float sum = dx * dx + dy * dy + dz * dz + dw * dw;
#pragma unroll
        for (int off = 16; off > 0; off >>= 1)
            sum += __shfl_xor_sync(0xffffffffu, sum, off);
        if (lane == 0) {
            float scv = -sqrtf(sum);
            if (j == 0) out[b] = scv;
            else        out[BATCH + b * N_NEG + (j - 1)] = scv;
        }
    }
}

// ---------------- launcher ------------------------------------------------
extern "C" void kernel_launch(void* const* d_in, const int* in_sizes, int n_in,
                              void* d_out, int out_size) {
    const int*   head    = (const int*)d_in[0];
    const int*   relidx  = (const int*)d_in[1];
    const int*   tail    = (const int*)d_in[2];
    const int*   neg     = (const int*)d_in[3];
    const int*   ei      = (const int*)d_in[4];
    const int*   et      = (const int*)d_in[5];
    const float* ent_tab = (const float*)d_in[6];
    const float* rel_tab = (const float*)d_in[7];
    const float* bases   = (const float*)d_in[8];
    const float* coeffs  = (const float*)d_in[9];
    const float* w_sl    = (const float*)d_in[10];
    const float* b_sl    = (const float*)d_in[11];
    const float* gamma   = (const float*)d_in[12];
    const float* beta    = (const float*)d_in[13];
    float* out = (float*)d_out;

    cudaFuncSetAttribute(k_gemm2,
                         cudaFuncAttributeMaxDynamicSharedMemorySize, SMEM_G);

    int ggrid = (QENT + 63) / 64;       // 391 blocks per quarter
    int egrid = QENT / 8;               // 3125 blocks per quarter

    // sort-by-dst + weights
    k_zero_all<<<(N_ENT + 255) / 256, 256>>>();
    k_hist<<<(N_EDGES + 255) / 256, 256>>>(ei);
    k_scan_part<<<NSCANB, 256>>>();
    k_scatter<<<(N_EDGES + 255) / 256, 256>>>(ei, et);
    k_wcat<<<(2 * 128 * 320 + 255) / 256, 256>>>(w_sl, bases);

    // layer 0 (4 L2-resident quarters)
    for (int q = 0; q < 4; q++) {
        k_edge_agg<<<egrid, 256>>>(coeffs, ent_tab, 0, q * QENT);
        k_gemm2<<<ggrid, 256, SMEM_G>>>(0, ent_tab, b_sl, 0, q * QENT);
    }
    k_bn_final<<<1, 128>>>(0, gamma, beta);

    // layer 1
    for (int q = 0; q < 4; q++) {
        k_edge_agg<<<egrid, 256>>>(coeffs + N_REL * N_BASES, ent_tab, 1, q * QENT);
        k_gemm2<<<ggrid, 256, SMEM_G>>>(1, ent_tab, b_sl, 1, q * QENT);
    }
    k_bn_final<<<1, 128>>>(1, gamma, beta);

    // scoring
    k_score<<<BATCH, 256>>>(head, relidx, tail, neg, rel_tab, out);
}